// round 3
// baseline (speedup 1.0000x reference)
#include <cuda_runtime.h>

// MXFP4 (E2M1) block fake-quant embedding gather — R3:
//   - 8 tokens/CTA (MLP=8 front-batched row loads)
//   - no per-element division: per-block precomputed decision thresholds
//     (|x| > bound*scale  ==  |x/scale| > bound, up to 1-ulp boundary events)
// d_in[0]: int32 indices, 16384 tokens
// d_in[1]: float32 embedding table, (50257, 1024)
// d_out  : float32 (16384, 1024)

#define F        1024
#define TOK_CTA  8

__device__ __forceinline__ float fp4_round_th(float x, float sc,
                                              float b0, float b1, float b2,
                                              float b3, float b4, float b5,
                                              float b6) {
    float a = fabsf(x);
    // strict '>' on midpoint thresholds == searchsorted(bounds, |x/scale|, 'left')
    float g;
    if (a > b3) {
        g = (a > b5) ? ((a > b6) ? 6.0f : 4.0f)
                     : ((a > b4) ? 3.0f : 2.0f);
    } else {
        g = (a > b1) ? ((a > b2) ? 1.5f : 1.0f)
                     : ((a > b0) ? 0.5f : 0.0f);
    }
    return copysignf(g * sc, x);
}

__global__ void __launch_bounds__(256)
mxfp4_embed_kernel(const int* __restrict__ idx,
                   const float* __restrict__ emb,
                   float* __restrict__ out) {
    const int t = threadIdx.x;                      // one float4 of a row
    const int base = blockIdx.x * TOK_CTA;

    // uniform index loads (L1 broadcast)
    int rows[TOK_CTA];
    #pragma unroll
    for (int j = 0; j < TOK_CTA; j++)
        rows[j] = __ldg(&idx[base + j]);

    // front-batch 8 independent row loads -> MLP=8
    float4 v[TOK_CTA];
    #pragma unroll
    for (int j = 0; j < TOK_CTA; j++)
        v[j] = reinterpret_cast<const float4*>(emb)[(size_t)rows[j] * (F / 4) + t];

    float4* dst = reinterpret_cast<float4*>(out) + (size_t)base * (F / 4) + t;

    #pragma unroll
    for (int j = 0; j < TOK_CTA; j++) {
        // max |.| over this thread's 4 values, then the 8-lane block group
        float m = fmaxf(fmaxf(fabsf(v[j].x), fabsf(v[j].y)),
                        fmaxf(fabsf(v[j].z), fabsf(v[j].w)));
        #pragma unroll
        for (int o = 4; o > 0; o >>= 1)
            m = fmaxf(m, __shfl_xor_sync(0xFFFFFFFFu, m, o, 8));

        const float sc = (m == 0.0f) ? 1.0f : (m / 6.0f);  // 1 div per token

        // per-block decision thresholds (7 FMULs amortized over 32 elems)
        const float b0 = 0.25f * sc, b1 = 0.75f * sc, b2 = 1.25f * sc,
                    b3 = 1.75f * sc, b4 = 2.50f * sc, b5 = 3.50f * sc,
                    b6 = 5.00f * sc;

        float4 r;
        r.x = fp4_round_th(v[j].x, sc, b0, b1, b2, b3, b4, b5, b6);
        r.y = fp4_round_th(v[j].y, sc, b0, b1, b2, b3, b4, b5, b6);
        r.z = fp4_round_th(v[j].z, sc, b0, b1, b2, b3, b4, b5, b6);
        r.w = fp4_round_th(v[j].w, sc, b0, b1, b2, b3, b4, b5, b6);

        dst[(size_t)j * (F / 4)] = r;
    }
}

extern "C" void kernel_launch(void* const* d_in, const int* in_sizes, int n_in,
                              void* d_out, int out_size) {
    const int*   idx = (const int*)d_in[0];
    const float* emb = (const float*)d_in[1];
    float*       out = (float*)d_out;

    const int tokens = in_sizes[0];              // 16384
    mxfp4_embed_kernel<<<tokens / TOK_CTA, 256>>>(idx, emb, out);
}

// round 5
// speedup vs baseline: 1.1751x; 1.1751x over previous
#include <cuda_runtime.h>
#include <cuda_fp16.h>
#include <cuda_fp4.h>

// MXFP4 (E2M1) block fake-quant embedding gather — R5:
//   - hardware E2M1 rounding via cuda_fp4.h intrinsics (correct .b8 cvt encoding)
//   - scale = m * (1/6) (1-ulp vs m/6), inv = __fdividef(6, m) (MUFU.RCP)
//   - 8 tokens/CTA, MLP=8 front-batched row loads
// d_in[0]: int32 indices, 16384 tokens
// d_in[1]: float32 embedding table, (50257, 1024)
// d_out  : float32 (16384, 1024)

#define F        1024
#define TOK_CTA  8

// Quantize a pair (x,y): a = (x*inv, y*inv) rounded to the E2M1 grid by HW,
// decoded back to exact grid values as f16 -> f32. Caller scales by sc.
__device__ __forceinline__ float2 fp4_pair(float x, float y, float inv) {
    float2 a = make_float2(x * inv, y * inv);
    __nv_fp4x2_storage_t p =
        __nv_cvt_float2_to_fp4x2(a, __NV_E2M1, cudaRoundNearest);
    __half2_raw hr = __nv_cvt_fp4x2_to_halfraw2(p, __NV_E2M1);
    __half2 h = *reinterpret_cast<__half2*>(&hr);
    return __half22float2(h);                      // exact grid values
}

__global__ void __launch_bounds__(256)
mxfp4_embed_kernel(const int* __restrict__ idx,
                   const float* __restrict__ emb,
                   float* __restrict__ out) {
    const int t = threadIdx.x;                      // one float4 of a row
    const int base = blockIdx.x * TOK_CTA;

    // uniform index loads (L1 broadcast)
    int rows[TOK_CTA];
    #pragma unroll
    for (int j = 0; j < TOK_CTA; j++)
        rows[j] = __ldg(&idx[base + j]);

    // front-batch 8 independent row loads -> MLP=8
    float4 v[TOK_CTA];
    #pragma unroll
    for (int j = 0; j < TOK_CTA; j++)
        v[j] = reinterpret_cast<const float4*>(emb)[(size_t)rows[j] * (F / 4) + t];

    float4* dst = reinterpret_cast<float4*>(out) + (size_t)base * (F / 4) + t;

    #pragma unroll
    for (int j = 0; j < TOK_CTA; j++) {
        // max |.| over this thread's 4 values, then the 8-lane block group
        float m = fmaxf(fmaxf(fabsf(v[j].x), fabsf(v[j].y)),
                        fmaxf(fabsf(v[j].z), fabsf(v[j].w)));
        #pragma unroll
        for (int o = 4; o > 0; o >>= 1)
            m = fmaxf(m, __shfl_xor_sync(0xFFFFFFFFu, m, o, 8));

        // scale and its reciprocal (m==0: all-zero block -> zeros out)
        const float sc  = (m == 0.0f) ? 1.0f : m * (1.0f / 6.0f);
        const float inv = (m == 0.0f) ? 0.0f : __fdividef(6.0f, m);

        float2 g0 = fp4_pair(v[j].x, v[j].y, inv);
        float2 g1 = fp4_pair(v[j].z, v[j].w, inv);

        float4 r;
        r.x = g0.x * sc;
        r.y = g0.y * sc;
        r.z = g1.x * sc;
        r.w = g1.y * sc;

        dst[(size_t)j * (F / 4)] = r;
    }
}

extern "C" void kernel_launch(void* const* d_in, const int* in_sizes, int n_in,
                              void* d_out, int out_size) {
    const int*   idx = (const int*)d_in[0];
    const float* emb = (const float*)d_in[1];
    float*       out = (float*)d_out;

    const int tokens = in_sizes[0];              // 16384
    mxfp4_embed_kernel<<<tokens / TOK_CTA, 256>>>(idx, emb, out);
}